// round 2
// baseline (speedup 1.0000x reference)
#include <cuda_runtime.h>

// Sizes (fixed by the problem, but derived from in_sizes at launch for safety)
#define NBLK 1024
#define NTHR 256

__device__ float g_partials[NBLK];

// Kernel 1: partial sums of S1 (recon) + 1.1*S2 (pca) per block.
__global__ __launch_bounds__(NTHR) void le_partials(
    const float* __restrict__ x,
    const float* __restrict__ decoded,
    const float* __restrict__ encoded,
    const float* __restrict__ latent,
    const float* __restrict__ rsrA,
    int B, int D, int E, int I)
{
    // rsrA is [E, I] row-major, E<=128, I<=20. Cache in shared, pad row stride
    // to 21 floats so warp-parallel-over-e accesses are bank-conflict-free.
    __shared__ float sA[128 * 21];
    for (int i = threadIdx.x; i < E * I; i += blockDim.x) {
        int e = i / I, k = i % I;
        sA[e * 21 + k] = rsrA[i];
    }
    __syncthreads();

    const int tid    = blockIdx.x * blockDim.x + threadIdx.x;
    const int stride = gridDim.x * blockDim.x;

    // ---- Term 1: sum (x - decoded)^2 over B*D, vectorized float4 ----
    float acc1 = 0.0f;
    {
        const float4* x4 = (const float4*)x;
        const float4* d4 = (const float4*)decoded;
        const int n4 = (B * D) >> 2;   // B*D divisible by 4
        for (int i = tid; i < n4; i += stride) {
            float4 a = x4[i];
            float4 b = d4[i];
            float dx = a.x - b.x, dy = a.y - b.y;
            float dz = a.z - b.z, dw = a.w - b.w;
            acc1 = fmaf(dx, dx, acc1);
            acc1 = fmaf(dy, dy, acc1);
            acc1 = fmaf(dz, dz, acc1);
            acc1 = fmaf(dw, dw, acc1);
        }
    }

    // ---- Term 2: sum (encoded - latent @ rsrA^T)^2 over B*E ----
    float acc2 = 0.0f;
    {
        const int n2 = B * E;
        for (int j = tid; j < n2; j += stride) {
            const int b = j >> 7;        // E == 128
            const int e = j & 127;
            const float* __restrict__ lrow = latent + b * I;
            const float* __restrict__ arow = sA + e * 21;
            float z = 0.0f;
            #pragma unroll
            for (int k = 0; k < 20; k++)     // I == 20
                z = fmaf(lrow[k], arow[k], z);
            float d = encoded[j] - z;
            acc2 = fmaf(d, d, acc2);
        }
    }

    // ---- Deterministic block reduction ----
    __shared__ float red[NTHR];
    red[threadIdx.x] = acc1 + 1.1f * acc2;
    __syncthreads();
    for (int s = NTHR / 2; s > 0; s >>= 1) {
        if (threadIdx.x < s) red[threadIdx.x] += red[threadIdx.x + s];
        __syncthreads();
    }
    if (threadIdx.x == 0) g_partials[blockIdx.x] = red[0];
}

// Kernel 2: Sg = sum((rsrA^T rsrA - I)^2), fold partials, write scalar.
__global__ __launch_bounds__(NTHR) void le_finalize(
    const float* __restrict__ rsrA,
    float* __restrict__ out,
    int B, int E, int I)
{
    __shared__ float sA[128 * 21];
    for (int i = threadIdx.x; i < E * I; i += blockDim.x) {
        int e = i / I, k = i % I;
        sA[e * 21 + k] = rsrA[i];
    }
    __syncthreads();

    // Gram term: 400 entries, each a dot over E=128.
    float sg = 0.0f;
    for (int t = threadIdx.x; t < I * I; t += blockDim.x) {
        const int i = t / 20, j = t % 20;   // I == 20
        float acc = 0.0f;
        #pragma unroll 8
        for (int e = 0; e < 128; e++)       // E == 128
            acc = fmaf(sA[e * 21 + i], sA[e * 21 + j], acc);
        if (i == j) acc -= 1.0f;
        sg = fmaf(acc, acc, sg);
    }

    // Sum the per-block partials.
    float p = 0.0f;
    for (int k = threadIdx.x; k < NBLK; k += blockDim.x)
        p += g_partials[k];

    // Combine with exact weights:
    //   loss = (S1 + 1.1*S2)/B + 0.1*Sg/(I*I)
    //        = ( P_total + (0.1*B/(I*I)) * Sg ) / B
    // For B=8192, I=20: 0.1*8192/400 = 2.048
    const float w = 0.1f * (float)B / (float)(I * I);
    __shared__ float red[NTHR];
    red[threadIdx.x] = p + w * sg;
    __syncthreads();
    for (int s = NTHR / 2; s > 0; s >>= 1) {
        if (threadIdx.x < s) red[threadIdx.x] += red[threadIdx.x + s];
        __syncthreads();
    }
    if (threadIdx.x == 0)
        out[0] = red[0] / (float)B;
}

extern "C" void kernel_launch(void* const* d_in, const int* in_sizes, int n_in,
                              void* d_out, int out_size)
{
    const float* x       = (const float*)d_in[0];
    const float* encoded = (const float*)d_in[1];
    const float* latent  = (const float*)d_in[2];
    const float* decoded = (const float*)d_in[3];
    const float* rsrA    = (const float*)d_in[4];

    const int I = 20;                       // INTRINSIC
    const int B = in_sizes[2] / I;          // latent [B, I]
    const int E = in_sizes[1] / B;          // encoded [B, E]
    const int D = in_sizes[0] / B;          // x [B, D]

    le_partials<<<NBLK, NTHR>>>(x, decoded, encoded, latent, rsrA, B, D, E, I);
    le_finalize<<<1, NTHR>>>(rsrA, (float*)d_out, B, E, I);
}

// round 3
// speedup vs baseline: 1.0111x; 1.0111x over previous
#include <cuda_runtime.h>

#define NBLK 1024
#define NTHR 256

__device__ float        g_partials[NBLK];
__device__ unsigned int g_ticket;   // zero-initialized; reset by last block each launch

__global__ __launch_bounds__(NTHR) void le_fused(
    const float* __restrict__ x,
    const float* __restrict__ decoded,
    const float* __restrict__ encoded,
    const float* __restrict__ latent,
    const float* __restrict__ rsrA,
    float* __restrict__ out,
    int B, int D, int E, int I)
{
    // rsrA [E=128, I=20] row-major cached in shared; row stride padded to 21
    // so lane-parallel-over-e access (stride 21 mod 32) is bank-conflict-free.
    __shared__ float sA[128 * 21];
    for (int i = threadIdx.x; i < E * I; i += blockDim.x) {
        int e = i / 20, k = i % 20;
        sA[e * 21 + k] = rsrA[i];
    }
    __syncthreads();

    const int tid    = blockIdx.x * blockDim.x + threadIdx.x;
    const int stride = gridDim.x * blockDim.x;
    const int n4 = (B * D) >> 2;   // float4 count for term 1
    const int n2 = B * E;          // element count for term 2

    const float4* __restrict__ x4 = (const float4*)x;
    const float4* __restrict__ d4 = (const float4*)decoded;

    float acc1 = 0.0f;   // sum (x - decoded)^2
    float acc2 = 0.0f;   // sum (encoded - latent@A^T)^2

    int i = tid, j = tid;

    // ---- Interleaved main loop: 2 term1 float4-iters per term2 element ----
    // (for B=8192,D=1024,E=128 each thread has exactly 8 term1 / 4 term2 iters)
    while (j < n2) {
        // issue term1 loads early (fill mem pipe while FMAs run)
        const int i0 = i, i1 = i + stride;
        const bool p0 = i0 < n4, p1 = i1 < n4;
        float4 a0, c0, a1, c1;
        if (p0) { a0 = x4[i0]; c0 = d4[i0]; }
        if (p1) { a1 = x4[i1]; c1 = d4[i1]; }
        if (p0) i += stride;
        if (p1) i += stride;

        // term2 element: residual of latent @ A^T against encoded
        {
            const int b = j >> 7;          // E == 128
            const int e = j & 127;
            const float4* __restrict__ l4 = (const float4*)(latent + b * 20); // 80B rows are 16B-aligned
            const float* __restrict__ ar  = sA + e * 21;
            float z = 0.0f;
            #pragma unroll
            for (int q = 0; q < 5; q++) {  // I == 20 = 5 * float4
                float4 L = l4[q];
                z = fmaf(L.x, ar[4 * q + 0], z);
                z = fmaf(L.y, ar[4 * q + 1], z);
                z = fmaf(L.z, ar[4 * q + 2], z);
                z = fmaf(L.w, ar[4 * q + 3], z);
            }
            float d = encoded[j] - z;
            acc2 = fmaf(d, d, acc2);
        }
        j += stride;

        // term1 FMAs (loads long since in flight)
        if (p0) {
            float dx = a0.x - c0.x, dy = a0.y - c0.y, dz = a0.z - c0.z, dw = a0.w - c0.w;
            acc1 = fmaf(dx, dx, acc1); acc1 = fmaf(dy, dy, acc1);
            acc1 = fmaf(dz, dz, acc1); acc1 = fmaf(dw, dw, acc1);
        }
        if (p1) {
            float dx = a1.x - c1.x, dy = a1.y - c1.y, dz = a1.z - c1.z, dw = a1.w - c1.w;
            acc1 = fmaf(dx, dx, acc1); acc1 = fmaf(dy, dy, acc1);
            acc1 = fmaf(dz, dz, acc1); acc1 = fmaf(dw, dw, acc1);
        }
    }
    // term1 remainder (none for the canonical shape, kept for safety)
    for (; i < n4; i += stride) {
        float4 a = x4[i], c = d4[i];
        float dx = a.x - c.x, dy = a.y - c.y, dz = a.z - c.z, dw = a.w - c.w;
        acc1 = fmaf(dx, dx, acc1); acc1 = fmaf(dy, dy, acc1);
        acc1 = fmaf(dz, dz, acc1); acc1 = fmaf(dw, dw, acc1);
    }

    // ---- Gram term (block 0 only): Sg = sum((A^T A - I)^2), folded with
    //      weight w = 0.1*B/(I*I) so the final /B gives 0.1*Sg/(I*I). ----
    float extra = 0.0f;
    if (blockIdx.x == 0) {
        float sg = 0.0f;
        for (int t = threadIdx.x; t < I * I; t += blockDim.x) {
            const int gi = t / 20, gj = t % 20;
            float acc = 0.0f;
            #pragma unroll 8
            for (int e = 0; e < 128; e++)
                acc = fmaf(sA[e * 21 + gi], sA[e * 21 + gj], acc);
            if (gi == gj) acc -= 1.0f;
            sg = fmaf(acc, acc, sg);
        }
        extra = (0.1f * (float)B / (float)(I * I)) * sg;
    }

    // ---- Deterministic block reduction ----
    __shared__ float red[NTHR];
    red[threadIdx.x] = acc1 + 1.1f * acc2 + extra;
    __syncthreads();
    for (int s = NTHR / 2; s > 0; s >>= 1) {
        if (threadIdx.x < s) red[threadIdx.x] += red[threadIdx.x + s];
        __syncthreads();
    }

    // ---- Last-block-done final reduction (single kernel, deterministic) ----
    __shared__ bool is_last;
    if (threadIdx.x == 0) {
        g_partials[blockIdx.x] = red[0];
        __threadfence();
        unsigned int t = atomicAdd(&g_ticket, 1u);
        is_last = (t == (unsigned int)(gridDim.x - 1));
    }
    __syncthreads();

    if (is_last) {
        __threadfence();
        // fixed-order sum: thread t takes k = t, t+NTHR, ... then tree reduce
        float p = 0.0f;
        for (int k = threadIdx.x; k < NBLK; k += NTHR)
            p += g_partials[k];
        red[threadIdx.x] = p;
        __syncthreads();
        for (int s = NTHR / 2; s > 0; s >>= 1) {
            if (threadIdx.x < s) red[threadIdx.x] += red[threadIdx.x + s];
            __syncthreads();
        }
        if (threadIdx.x == 0) {
            out[0] = red[0] / (float)B;
            g_ticket = 0;   // reset for next graph replay
        }
    }
}

extern "C" void kernel_launch(void* const* d_in, const int* in_sizes, int n_in,
                              void* d_out, int out_size)
{
    const float* x       = (const float*)d_in[0];
    const float* encoded = (const float*)d_in[1];
    const float* latent  = (const float*)d_in[2];
    const float* decoded = (const float*)d_in[3];
    const float* rsrA    = (const float*)d_in[4];

    const int I = 20;                  // INTRINSIC
    const int B = in_sizes[2] / I;     // latent [B, I]
    const int E = in_sizes[1] / B;     // encoded [B, E]
    const int D = in_sizes[0] / B;     // x [B, D]

    le_fused<<<NBLK, NTHR>>>(x, decoded, encoded, latent, rsrA,
                             (float*)d_out, B, D, E, I);
}

// round 4
// speedup vs baseline: 1.2297x; 1.2162x over previous
#include <cuda_runtime.h>

#define NBLK 592          // 4 blocks/SM * 148 SMs -> exactly one wave
#define NTHR 256

__device__ float        g_partials[NBLK];
__device__ unsigned int g_ticket;   // zero-init; reset by last block each launch

__global__ __launch_bounds__(NTHR) void le_fused(
    const float* __restrict__ x,
    const float* __restrict__ decoded,
    const float* __restrict__ encoded,
    const float* __restrict__ latent,
    const float* __restrict__ rsrA,
    float* __restrict__ out,
    int B, int D, int E, int I)
{
    // rsrA [E=128, I=20] cached in shared; row stride 21 -> conflict-free
    // when consecutive lanes read consecutive e rows.
    __shared__ float sA[128 * 21];
    for (int i = threadIdx.x; i < E * I; i += blockDim.x) {
        int e = i / 20, k = i % 20;
        sA[e * 21 + k] = rsrA[i];
    }
    __syncthreads();

    const int tid    = blockIdx.x * blockDim.x + threadIdx.x;
    const int stride = gridDim.x * blockDim.x;
    const int n4 = (B * D) >> 2;   // term-1 float4 count
    const int n2 = B * E;          // term-2 element count

    const float4* __restrict__ x4 = (const float4*)x;
    const float4* __restrict__ d4 = (const float4*)decoded;

    // ======== Phase 1: sum (x - decoded)^2, 4x unrolled (8 LDG.128 in flight) ====
    float acc1 = 0.0f;
    {
        int i = tid;
        const int s = stride;
        for (; i + 3 * s < n4; i += 4 * s) {
            float4 a0 = x4[i];         float4 c0 = d4[i];
            float4 a1 = x4[i + s];     float4 c1 = d4[i + s];
            float4 a2 = x4[i + 2*s];   float4 c2 = d4[i + 2*s];
            float4 a3 = x4[i + 3*s];   float4 c3 = d4[i + 3*s];

            float t;
            t = a0.x - c0.x; acc1 = fmaf(t, t, acc1);
            t = a0.y - c0.y; acc1 = fmaf(t, t, acc1);
            t = a0.z - c0.z; acc1 = fmaf(t, t, acc1);
            t = a0.w - c0.w; acc1 = fmaf(t, t, acc1);
            t = a1.x - c1.x; acc1 = fmaf(t, t, acc1);
            t = a1.y - c1.y; acc1 = fmaf(t, t, acc1);
            t = a1.z - c1.z; acc1 = fmaf(t, t, acc1);
            t = a1.w - c1.w; acc1 = fmaf(t, t, acc1);
            t = a2.x - c2.x; acc1 = fmaf(t, t, acc1);
            t = a2.y - c2.y; acc1 = fmaf(t, t, acc1);
            t = a2.z - c2.z; acc1 = fmaf(t, t, acc1);
            t = a2.w - c2.w; acc1 = fmaf(t, t, acc1);
            t = a3.x - c3.x; acc1 = fmaf(t, t, acc1);
            t = a3.y - c3.y; acc1 = fmaf(t, t, acc1);
            t = a3.z - c3.z; acc1 = fmaf(t, t, acc1);
            t = a3.w - c3.w; acc1 = fmaf(t, t, acc1);
        }
        for (; i < n4; i += s) {
            float4 a = x4[i], c = d4[i];
            float t;
            t = a.x - c.x; acc1 = fmaf(t, t, acc1);
            t = a.y - c.y; acc1 = fmaf(t, t, acc1);
            t = a.z - c.z; acc1 = fmaf(t, t, acc1);
            t = a.w - c.w; acc1 = fmaf(t, t, acc1);
        }
    }

    // ======== Phase 2: sum (encoded - latent@A^T)^2, 4 independent slots ========
    float acc2 = 0.0f;
    {
        int j = tid;
        const int s = stride;
        for (; j + 3 * s < n2; j += 4 * s) {
            float z0 = 0.f, z1 = 0.f, z2 = 0.f, z3 = 0.f;
            const int j0 = j, j1 = j + s, j2 = j + 2*s, j3 = j + 3*s;
            const float4* __restrict__ L0 = (const float4*)(latent + (j0 >> 7) * 20);
            const float4* __restrict__ L1 = (const float4*)(latent + (j1 >> 7) * 20);
            const float4* __restrict__ L2 = (const float4*)(latent + (j2 >> 7) * 20);
            const float4* __restrict__ L3 = (const float4*)(latent + (j3 >> 7) * 20);
            const float* __restrict__ A0 = sA + (j0 & 127) * 21;
            const float* __restrict__ A1 = sA + (j1 & 127) * 21;
            const float* __restrict__ A2 = sA + (j2 & 127) * 21;
            const float* __restrict__ A3 = sA + (j3 & 127) * 21;
            float e0 = encoded[j0], e1 = encoded[j1],
                  e2 = encoded[j2], e3 = encoded[j3];
            #pragma unroll
            for (int q = 0; q < 5; q++) {           // I == 20 = 5 float4
                float4 l0 = L0[q], l1 = L1[q], l2 = L2[q], l3 = L3[q];
                z0 = fmaf(l0.x, A0[4*q+0], z0); z0 = fmaf(l0.y, A0[4*q+1], z0);
                z0 = fmaf(l0.z, A0[4*q+2], z0); z0 = fmaf(l0.w, A0[4*q+3], z0);
                z1 = fmaf(l1.x, A1[4*q+0], z1); z1 = fmaf(l1.y, A1[4*q+1], z1);
                z1 = fmaf(l1.z, A1[4*q+2], z1); z1 = fmaf(l1.w, A1[4*q+3], z1);
                z2 = fmaf(l2.x, A2[4*q+0], z2); z2 = fmaf(l2.y, A2[4*q+1], z2);
                z2 = fmaf(l2.z, A2[4*q+2], z2); z2 = fmaf(l2.w, A2[4*q+3], z2);
                z3 = fmaf(l3.x, A3[4*q+0], z3); z3 = fmaf(l3.y, A3[4*q+1], z3);
                z3 = fmaf(l3.z, A3[4*q+2], z3); z3 = fmaf(l3.w, A3[4*q+3], z3);
            }
            float d;
            d = e0 - z0; acc2 = fmaf(d, d, acc2);
            d = e1 - z1; acc2 = fmaf(d, d, acc2);
            d = e2 - z2; acc2 = fmaf(d, d, acc2);
            d = e3 - z3; acc2 = fmaf(d, d, acc2);
        }
        for (; j < n2; j += s) {
            const float4* __restrict__ L = (const float4*)(latent + (j >> 7) * 20);
            const float* __restrict__ A = sA + (j & 127) * 21;
            float z = 0.f;
            #pragma unroll
            for (int q = 0; q < 5; q++) {
                float4 l = L[q];
                z = fmaf(l.x, A[4*q+0], z); z = fmaf(l.y, A[4*q+1], z);
                z = fmaf(l.z, A[4*q+2], z); z = fmaf(l.w, A[4*q+3], z);
            }
            float d = encoded[j] - z;
            acc2 = fmaf(d, d, acc2);
        }
    }

    // ======== Gram term (block 0): w*Sg with w = 0.1*B/(I*I) ========
    float extra = 0.0f;
    if (blockIdx.x == 0) {
        float sg = 0.0f;
        for (int t = threadIdx.x; t < I * I; t += blockDim.x) {
            const int gi = t / 20, gj = t % 20;
            float acc = 0.0f;
            #pragma unroll 8
            for (int e = 0; e < 128; e++)
                acc = fmaf(sA[e * 21 + gi], sA[e * 21 + gj], acc);
            if (gi == gj) acc -= 1.0f;
            sg = fmaf(acc, acc, sg);
        }
        extra = (0.1f * (float)B / (float)(I * I)) * sg;
    }

    // ======== Deterministic block reduction ========
    __shared__ float red[NTHR];
    red[threadIdx.x] = acc1 + 1.1f * acc2 + extra;
    __syncthreads();
    for (int s = NTHR / 2; s > 0; s >>= 1) {
        if (threadIdx.x < s) red[threadIdx.x] += red[threadIdx.x + s];
        __syncthreads();
    }

    // ======== Last-block final reduction ========
    __shared__ bool is_last;
    if (threadIdx.x == 0) {
        g_partials[blockIdx.x] = red[0];
        __threadfence();
        unsigned int t = atomicAdd(&g_ticket, 1u);
        is_last = (t == (unsigned int)(gridDim.x - 1));
    }
    __syncthreads();

    if (is_last) {
        __threadfence();
        float p = 0.0f;
        for (int k = threadIdx.x; k < NBLK; k += NTHR)
            p += g_partials[k];
        red[threadIdx.x] = p;
        __syncthreads();
        for (int s = NTHR / 2; s > 0; s >>= 1) {
            if (threadIdx.x < s) red[threadIdx.x] += red[threadIdx.x + s];
            __syncthreads();
        }
        if (threadIdx.x == 0) {
            out[0] = red[0] / (float)B;
            g_ticket = 0;
        }
    }
}

extern "C" void kernel_launch(void* const* d_in, const int* in_sizes, int n_in,
                              void* d_out, int out_size)
{
    const float* x       = (const float*)d_in[0];
    const float* encoded = (const float*)d_in[1];
    const float* latent  = (const float*)d_in[2];
    const float* decoded = (const float*)d_in[3];
    const float* rsrA    = (const float*)d_in[4];

    const int I = 20;                  // INTRINSIC
    const int B = in_sizes[2] / I;     // latent [B, I]
    const int E = in_sizes[1] / B;     // encoded [B, E]
    const int D = in_sizes[0] / B;     // x [B, D]

    le_fused<<<NBLK, NTHR>>>(x, decoded, encoded, latent, rsrA,
                             (float*)d_out, B, D, E, I);
}